// round 9
// baseline (speedup 1.0000x reference)
#include <cuda_runtime.h>

typedef unsigned long long ull;

#define THREADS 256
#define SCALE_F 0.125f
#define FULLM   0xffffffffu
#define PAD     66

// smem float offsets
#define QSM 0
#define KSM (64 * PAD)          // 4224
#define GSM (2 * 64 * PAD)      // 8448  (pe^T in prologue, gate tiles in loop)
#define LGT (3 * 64 * PAD)      // 12672
#define SMEM_FLOATS (4 * 64 * PAD)
#define SMEM_BYTES  (SMEM_FLOATS * 4)   // 67584 B -> 3 CTAs/SM

__device__ __forceinline__ ull fma2(ull a, ull b, ull c) {
    ull d;
    asm("fma.rn.f32x2 %0, %1, %2, %3;" : "=l"(d) : "l"(a), "l"(b), "l"(c));
    return d;
}
__device__ __forceinline__ float hsum2(ull a) {
    unsigned lo, hi;
    asm("mov.b64 {%0, %1}, %2;" : "=r"(lo), "=r"(hi) : "l"(a));
    return __uint_as_float(lo) + __uint_as_float(hi);
}
__device__ __forceinline__ float sigm(float x) {
    return __fdividef(1.0f, 1.0f + __expf(-x));
}
__device__ __forceinline__ void cp8(unsigned dst, const void* src) {
    asm volatile("cp.async.ca.shared.global [%0], [%1], 8;\n" :: "r"(dst), "l"(src));
}

// async copy of a 64x64 row-major gmem tile into smem [64][PAD] (8B chunks; PAD=66
// keeps gemm LDS.64 conflict-free but allows only 8B smem alignment)
__device__ __forceinline__ void kload_async(const float* __restrict__ src,
                                            float* ksm, int tid) {
    unsigned base = (unsigned)__cvta_generic_to_shared(ksm);
    #pragma unroll
    for (int i = 0; i < 8; ++i) {
        int f   = tid + i * THREADS;      // 8B-chunk id, 2048 total
        int row = f >> 5;                 // 32 chunks per 64-float row
        int d   = (f & 31) * 2;
        cp8(base + (unsigned)(row * PAD + d) * 4u, src + row * 64 + d);
    }
    asm volatile("cp.async.commit_group;\n");
}

// synchronous 64x64 tile load (prologue q/base only)
__device__ __forceinline__ void load64(const float* __restrict__ src, float* dst, int tid) {
    #pragma unroll
    for (int r = 0; r < 4; ++r) {
        int f   = tid + r * THREADS;
        int row = f >> 4;
        int dp  = (f & 15) * 4;
        float4 v = *(const float4*)(src + row * 64 + dp);
        float* p = dst + row * PAD + dp;
        *(float2*)p       = make_float2(v.x, v.y);
        *(float2*)(p + 2) = make_float2(v.z, v.w);
    }
}

// 64x64x64 register-tiled GEMM: dst[row][key] = qs[row]·ks[key]  (+sigmoid if GATE)
template <bool GATE>
__device__ __forceinline__ void gemm64(const float* qs, const float* ks, float* dst,
                                       int lane, int w)
{
    const int row0 = (w >> 2) * 32 + (lane >> 2) * 4;
    const int key0 = (w & 3) * 16 + (lane & 3) * 4;
    ull acc[4][4];
    #pragma unroll
    for (int i = 0; i < 4; ++i)
        #pragma unroll
        for (int j = 0; j < 4; ++j) acc[i][j] = 0ull;

    #pragma unroll 8
    for (int d = 0; d < 64; d += 2) {
        ull qv[4], kv[4];
        #pragma unroll
        for (int i = 0; i < 4; ++i) qv[i] = *(const ull*)(qs + (row0 + i) * PAD + d);
        #pragma unroll
        for (int j = 0; j < 4; ++j) kv[j] = *(const ull*)(ks + (key0 + j) * PAD + d);
        #pragma unroll
        for (int i = 0; i < 4; ++i)
            #pragma unroll
            for (int j = 0; j < 4; ++j)
                acc[i][j] = fma2(qv[i], kv[j], acc[i][j]);
    }
    #pragma unroll
    for (int i = 0; i < 4; ++i) {
        float v0 = hsum2(acc[i][0]), v1 = hsum2(acc[i][1]);
        float v2 = hsum2(acc[i][2]), v3 = hsum2(acc[i][3]);
        if (GATE) {
            v0 = sigm(v0 * SCALE_F); v1 = sigm(v1 * SCALE_F);
            v2 = sigm(v2 * SCALE_F); v3 = sigm(v3 * SCALE_F);
        }
        float* p = dst + (row0 + i) * PAD + key0;
        *(float2*)p       = make_float2(v0, v1);
        *(float2*)(p + 2) = make_float2(v2, v3);
    }
}

__global__ void __launch_bounds__(THREADS, 3)
cope_kernel(const float* __restrict__ q, const float* __restrict__ kmat,
            const float* __restrict__ pe, const int* __restrict__ flagp,
            float* __restrict__ out)
{
    extern __shared__ float sm[];
    float* qsm = sm + QSM;
    float* ksm = sm + KSM;
    float* gsm = sm + GSM;       // pe^T now, gate tiles later
    float* lgt = sm + LGT;

    const int tid  = threadIdx.x;
    const int w    = tid >> 5;
    const int lane = tid & 31;
    const int b    = blockIdx.x >> 4;
    const int rb   = blockIdx.x & 15;
    const int rowg0 = b * 1024 + rb * 64;
    const float* kb = kmat + b * 1024 * 64;
    const int flag = *flagp;

    // ---- prologue: prefetch highest k tile; pe^T -> gsm; base rows -> qsm
    kload_async(kb + 15 * 4096, ksm, tid);
    for (int i = tid; i < 4096; i += THREADS) {       // pe[d][n] -> gsm[n][d]
        int d = i >> 6, n = i & 63;
        gsm[n * PAD + d] = pe[i];
    }
    load64((flag ? q : kmat) + rowg0 * 64, qsm, tid);
    __syncthreads();

    gemm64<false>(qsm, gsm, lgt, lane, w);            // logits_int table
    __syncthreads();
    if (tid < 64) lgt[tid * PAD + 64] = 0.0f;         // guard: pos==63 -> w=0 exact
    if (!flag) load64(q + rowg0 * 64, qsm, tid);      // gates always use q
    asm volatile("cp.async.wait_group 0;\n");
    __syncthreads();                                  // ksm(t15), lgt, qsm all visible

    // ---- tile loop: gemm -> (prefetch) -> scan -> vote; carries live in registers
    float cl[8];
    #pragma unroll
    for (int rr = 0; rr < 8; ++rr) cl[rr] = 0.0f;

    int kend = 0;
    for (int T = 15; ; --T) {
        gemm64<true>(qsm, ksm, gsm, lane, w);         // sigmoid gates into gsm
        __syncthreads();                              // gsm ready; ksm reads done
        if (T > 0) kload_async(kb + (T - 1) * 4096, ksm, tid);  // lands during scan

        // scan: warp w owns rows w*8..w*8+7; two 32-key chunks, high first
        #pragma unroll
        for (int c = 1; c >= 0; --c) {
            float s[8];
            #pragma unroll
            for (int rr = 0; rr < 8; ++rr)
                s[rr] = gsm[(w * 8 + rr) * PAD + c * 32 + lane];
            #pragma unroll
            for (int off = 1; off < 32; off <<= 1) {
                #pragma unroll
                for (int rr = 0; rr < 8; ++rr) {
                    float u = __shfl_down_sync(FULLM, s[rr], off);
                    if (lane + off < 32) s[rr] += u;
                }
            }
            #pragma unroll
            for (int rr = 0; rr < 8; ++rr) {
                float pos = fminf(cl[rr] + s[rr], 63.0f);
                float pf  = floorf(pos);
                int   ip  = (int)pf;
                float wt  = pos - pf;
                const float* lr = lgt + (w * 8 + rr) * PAD;
                float val = lr[ip + 1] * wt + lr[ip] * (1.0f - wt);
                __stcs(out + (rowg0 + w * 8 + rr) * 1024 + T * 64 + c * 32 + lane, val);
            }
            #pragma unroll
            for (int rr = 0; rr < 8; ++rr)
                cl[rr] += __shfl_sync(FULLM, s[rr], 0);
        }

        if (T > 0) asm volatile("cp.async.wait_group 0;\n");
        bool sat = true;
        #pragma unroll
        for (int rr = 0; rr < 8; ++rr) sat = sat && (cl[rr] >= 63.0f);
        bool alldone = __syncthreads_and(sat);        // also orders gsm reuse + ksm fill
        if (alldone) { kend = T * 64; break; }
        if (T == 0)  { kend = 0;      break; }
    }

    // ---- saturated bulk fill: keys [0, kend) = logits_int[row][63]
    if (kend > 0) {
        #pragma unroll
        for (int rr = 0; rr < 8; ++rr) {
            int r = w * 8 + rr;
            float v = lgt[r * PAD + 63];
            float4 vv = make_float4(v, v, v, v);
            float* dst = out + (rowg0 + r) * 1024;
            for (int c = 4 * lane; c < kend; c += 128)
                __stcs((float4*)(dst + c), vv);
        }
    }
}

extern "C" void kernel_launch(void* const* d_in, const int* in_sizes, int n_in,
                              void* d_out, int out_size) {
    const float* q    = (const float*)d_in[0];
    const float* k    = (const float*)d_in[1];
    // d_in[2] = v (unused in mode 0)
    const float* pe   = (const float*)d_in[3];
    // d_in[4] = w_k (unused)
    const int*   flag = (const int*)d_in[5];
    float* out = (float*)d_out;

    cudaFuncSetAttribute(cope_kernel, cudaFuncAttributeMaxDynamicSharedMemorySize, SMEM_BYTES);
    const int grid = 32 * 16;   // 512 CTAs: 32 batches x 16 row-blocks of 64
    cope_kernel<<<grid, THREADS, SMEM_BYTES>>>(q, k, pe, flag, out);
}

// round 11
// speedup vs baseline: 1.2358x; 1.2358x over previous
#include <cuda_runtime.h>

typedef unsigned long long ull;

#define THREADS 256
#define SCALE_F 0.125f
#define FULLM   0xffffffffu
#define PAD     68

// smem float offsets
#define QSM 0
#define KSM (64 * PAD)          // 4352
#define GSM (2 * 64 * PAD)      // 8704  (pe^T in prologue, gate tiles in loop)
#define LGT (3 * 64 * PAD)      // 13056
#define SMEM_FLOATS (4 * 64 * PAD)
#define SMEM_BYTES  (SMEM_FLOATS * 4)   // 69632 B -> 3 CTAs/SM

__device__ __forceinline__ ull fma2(ull a, ull b, ull c) {
    ull d;
    asm("fma.rn.f32x2 %0, %1, %2, %3;" : "=l"(d) : "l"(a), "l"(b), "l"(c));
    return d;
}
__device__ __forceinline__ float hsum2(ull a) {
    unsigned lo, hi;
    asm("mov.b64 {%0, %1}, %2;" : "=r"(lo), "=r"(hi) : "l"(a));
    return __uint_as_float(lo) + __uint_as_float(hi);
}
__device__ __forceinline__ float sigm(float x) {
    return __fdividef(1.0f, 1.0f + __expf(-x));
}
__device__ __forceinline__ void cp16(unsigned dst, const void* src) {
    asm volatile("cp.async.cg.shared.global [%0], [%1], 16;\n" :: "r"(dst), "l"(src));
}

// async copy of a 64x64 row-major gmem tile into smem [64][PAD]
// PAD=68 -> row stride 272 B (16B-aligned) -> legal 16B cp.async, 4 ops/thread
__device__ __forceinline__ void kload_async(const float* __restrict__ src,
                                            float* ksm, int tid) {
    unsigned base = (unsigned)__cvta_generic_to_shared(ksm);
    #pragma unroll
    for (int i = 0; i < 4; ++i) {
        int f   = tid + i * THREADS;      // 16B-chunk id, 1024 total
        int row = f >> 4;                 // 16 chunks per 64-float row
        int d   = (f & 15) * 4;
        cp16(base + (unsigned)(row * PAD + d) * 4u, src + row * 64 + d);
    }
    asm volatile("cp.async.commit_group;\n");
}

// synchronous 64x64 tile load (prologue q/base only)
__device__ __forceinline__ void load64(const float* __restrict__ src, float* dst, int tid) {
    #pragma unroll
    for (int r = 0; r < 4; ++r) {
        int f   = tid + r * THREADS;
        int row = f >> 4;
        int dp  = (f & 15) * 4;
        float4 v = *(const float4*)(src + row * 64 + dp);
        *(float4*)(dst + row * PAD + dp) = v;
    }
}

// 64x64x64 register-tiled GEMM: dst[row][key] = qs[row]·ks[key]  (+sigmoid if GATE)
template <bool GATE>
__device__ __forceinline__ void gemm64(const float* qs, const float* ks, float* dst,
                                       int lane, int w)
{
    const int row0 = (w >> 2) * 32 + (lane >> 2) * 4;
    const int key0 = (w & 3) * 16 + (lane & 3) * 4;
    ull acc[4][4];
    #pragma unroll
    for (int i = 0; i < 4; ++i)
        #pragma unroll
        for (int j = 0; j < 4; ++j) acc[i][j] = 0ull;

    #pragma unroll 8
    for (int d = 0; d < 64; d += 2) {
        ull qv[4], kv[4];
        #pragma unroll
        for (int i = 0; i < 4; ++i) qv[i] = *(const ull*)(qs + (row0 + i) * PAD + d);
        #pragma unroll
        for (int j = 0; j < 4; ++j) kv[j] = *(const ull*)(ks + (key0 + j) * PAD + d);
        #pragma unroll
        for (int i = 0; i < 4; ++i)
            #pragma unroll
            for (int j = 0; j < 4; ++j)
                acc[i][j] = fma2(qv[i], kv[j], acc[i][j]);
    }
    #pragma unroll
    for (int i = 0; i < 4; ++i) {
        float v0 = hsum2(acc[i][0]), v1 = hsum2(acc[i][1]);
        float v2 = hsum2(acc[i][2]), v3 = hsum2(acc[i][3]);
        if (GATE) {
            v0 = sigm(v0 * SCALE_F); v1 = sigm(v1 * SCALE_F);
            v2 = sigm(v2 * SCALE_F); v3 = sigm(v3 * SCALE_F);
        }
        float* p = dst + (row0 + i) * PAD + key0;
        *(float4*)p = make_float4(v0, v1, v2, v3);
    }
}

__global__ void __launch_bounds__(THREADS, 3)
cope_kernel(const float* __restrict__ q, const float* __restrict__ kmat,
            const float* __restrict__ pe, const int* __restrict__ flagp,
            float* __restrict__ out)
{
    extern __shared__ float sm[];
    float* qsm = sm + QSM;
    float* ksm = sm + KSM;
    float* gsm = sm + GSM;       // pe^T now, gate tiles later
    float* lgt = sm + LGT;

    const int tid  = threadIdx.x;
    const int w    = tid >> 5;
    const int lane = tid & 31;
    const int b    = blockIdx.x >> 4;
    const int rb   = blockIdx.x & 15;
    const int rowg0 = b * 1024 + rb * 64;
    const float* kb = kmat + b * 1024 * 64;
    const int flag = *flagp;

    // ---- prologue: prefetch highest k tile; pe^T -> gsm; base rows -> qsm
    kload_async(kb + 15 * 4096, ksm, tid);
    for (int i = tid; i < 4096; i += THREADS) {       // pe[d][n] -> gsm[n][d]
        int d = i >> 6, n = i & 63;
        gsm[n * PAD + d] = pe[i];
    }
    load64((flag ? q : kmat) + rowg0 * 64, qsm, tid);
    __syncthreads();

    gemm64<false>(qsm, gsm, lgt, lane, w);            // logits_int table
    __syncthreads();
    if (tid < 64) lgt[tid * PAD + 64] = 0.0f;         // guard: pos==63 -> w=0 exact
    if (!flag) load64(q + rowg0 * 64, qsm, tid);      // gates always use q
    asm volatile("cp.async.wait_group 0;\n");
    __syncthreads();                                  // ksm(t15), lgt, qsm all visible

    // ---- tile loop: gemm -> prefetch -> scan -> vote; carries live in registers
    float cl[8];
    #pragma unroll
    for (int rr = 0; rr < 8; ++rr) cl[rr] = 0.0f;

    int kend = 0;
    for (int T = 15; ; --T) {
        gemm64<true>(qsm, ksm, gsm, lane, w);         // sigmoid gates into gsm
        __syncthreads();                              // gsm ready; ksm reads done
        if (T > 0) kload_async(kb + (T - 1) * 4096, ksm, tid);  // lands during scan

        // scan: warp w owns rows w*8..w*8+7; two 32-key chunks, high first
        #pragma unroll
        for (int c = 1; c >= 0; --c) {
            float s[8];
            #pragma unroll
            for (int rr = 0; rr < 8; ++rr)
                s[rr] = gsm[(w * 8 + rr) * PAD + c * 32 + lane];
            #pragma unroll
            for (int off = 1; off < 32; off <<= 1) {
                #pragma unroll
                for (int rr = 0; rr < 8; ++rr) {
                    float u = __shfl_down_sync(FULLM, s[rr], off);
                    if (lane + off < 32) s[rr] += u;
                }
            }
            #pragma unroll
            for (int rr = 0; rr < 8; ++rr) {
                float pos = fminf(cl[rr] + s[rr], 63.0f);
                float pf  = floorf(pos);
                int   ip  = (int)pf;
                float wt  = pos - pf;
                const float* lr = lgt + (w * 8 + rr) * PAD;
                float val = lr[ip + 1] * wt + lr[ip] * (1.0f - wt);
                __stcs(out + (rowg0 + w * 8 + rr) * 1024 + T * 64 + c * 32 + lane, val);
            }
            #pragma unroll
            for (int rr = 0; rr < 8; ++rr)
                cl[rr] += __shfl_sync(FULLM, s[rr], 0);
        }

        if (T > 0) asm volatile("cp.async.wait_group 0;\n");
        bool sat = true;
        #pragma unroll
        for (int rr = 0; rr < 8; ++rr) sat = sat && (cl[rr] >= 63.0f);
        bool alldone = __syncthreads_and(sat);        // also orders gsm reuse + ksm fill
        if (alldone) { kend = T * 64; break; }
        if (T == 0)  { kend = 0;      break; }
    }

    // ---- saturated bulk fill: keys [0, kend) = logits_int[row][63]
    if (kend > 0) {
        #pragma unroll
        for (int rr = 0; rr < 8; ++rr) {
            int r = w * 8 + rr;
            float v = lgt[r * PAD + 63];
            float4 vv = make_float4(v, v, v, v);
            float* dst = out + (rowg0 + r) * 1024;
            for (int c = 4 * lane; c < kend; c += 128)
                __stcs((float4*)(dst + c), vv);
        }
    }
}

extern "C" void kernel_launch(void* const* d_in, const int* in_sizes, int n_in,
                              void* d_out, int out_size) {
    const float* q    = (const float*)d_in[0];
    const float* k    = (const float*)d_in[1];
    // d_in[2] = v (unused in mode 0)
    const float* pe   = (const float*)d_in[3];
    // d_in[4] = w_k (unused)
    const int*   flag = (const int*)d_in[5];
    float* out = (float*)d_out;

    cudaFuncSetAttribute(cope_kernel, cudaFuncAttributeMaxDynamicSharedMemorySize, SMEM_BYTES);
    const int grid = 32 * 16;   // 512 CTAs: 32 batches x 16 row-blocks of 64
    cope_kernel<<<grid, THREADS, SMEM_BYTES>>>(q, k, pe, flag, out);
}